// round 8
// baseline (speedup 1.0000x reference)
#include <cuda_runtime.h>
#include <cuda_bf16.h>

// loss = sum_{b,c,s,h,w} (out[b,c,2s,h,w] - target[b,c,2s+1,h,w])^2 / (C*H*Wd * W/2)
// B=8, C=32, W=16 (s=0..7), H=128, Wd=128.
//
// 2048 slabs (g = flattened b,c,s). Slab g:
//   out float4 base : out4 + (g<<13)          (4096 float4 = 64 KB)
//   tgt float4 base : tgt4 + (g<<13) + 4096   (4096 float4 = 64 KB)
//
// Kernel A: one CTA per slab, clean streaming loop, plain partial store,
//           per-block cudaTriggerProgrammaticLaunchCompletion().
// Kernel B: final sum, launched with PDL (programmaticStreamSerialization) so
//           its launch latency overlaps A; it waits via
//           cudaGridDependencySynchronize() before reading partials.

#define NBLOCKS 2048
#define NTHREADS 256
#define PER_THREAD 16       // 4096 / 256
#define FIN_THREADS 256
#define FIN_PER_THREAD (NBLOCKS / FIN_THREADS)   // 8

__device__ float g_partials[NBLOCKS];

__global__ __launch_bounds__(NTHREADS) void cont_loss_partial_kernel(
    const float4* __restrict__ out4, const float4* __restrict__ tgt4)
{
    const long long base = ((long long)blockIdx.x << 13);
    const float4* __restrict__ op = out4 + base + threadIdx.x;
    const float4* __restrict__ tp = tgt4 + base + 4096 + threadIdx.x;

    float a0 = 0.0f, a1 = 0.0f, a2 = 0.0f, a3 = 0.0f;
    #pragma unroll
    for (int k = 0; k < PER_THREAD; k++) {
        float4 o = op[k * NTHREADS];
        float4 t = tp[k * NTHREADS];
        float d0 = o.x - t.x;
        float d1 = o.y - t.y;
        float d2 = o.z - t.z;
        float d3 = o.w - t.w;
        a0 = fmaf(d0, d0, a0);
        a1 = fmaf(d1, d1, a1);
        a2 = fmaf(d2, d2, a2);
        a3 = fmaf(d3, d3, a3);
    }
    float acc = (a0 + a1) + (a2 + a3);

    // deterministic warp-shuffle tree + cross-warp via smem
    #pragma unroll
    for (int ofs = 16; ofs > 0; ofs >>= 1)
        acc += __shfl_down_sync(0xFFFFFFFFu, acc, ofs);

    __shared__ float swarp[NTHREADS / 32];
    const int lane = threadIdx.x & 31;
    const int wid  = threadIdx.x >> 5;
    if (lane == 0) swarp[wid] = acc;
    __syncthreads();

    if (threadIdx.x == 0) {
        float blk = 0.0f;
        #pragma unroll
        for (int w = 0; w < NTHREADS / 32; w++) blk += swarp[w];
        g_partials[blockIdx.x] = blk;
    }

    // allow the PDL secondary to begin launching as blocks drain
    cudaTriggerProgrammaticLaunchCompletion();
}

__global__ __launch_bounds__(FIN_THREADS) void cont_loss_final_kernel(float* __restrict__ out)
{
    // Pre-launched via PDL: park until the primary grid's memory is visible.
    cudaGridDependencySynchronize();

    double dacc = 0.0;
    #pragma unroll
    for (int k = 0; k < FIN_PER_THREAD; k++)
        dacc += (double)g_partials[threadIdx.x + k * FIN_THREADS];

    #pragma unroll
    for (int ofs = 16; ofs > 0; ofs >>= 1)
        dacc += __shfl_down_sync(0xFFFFFFFFu, dacc, ofs);

    __shared__ double dwarp[FIN_THREADS / 32];
    const int lane = threadIdx.x & 31;
    const int wid  = threadIdx.x >> 5;
    if (lane == 0) dwarp[wid] = dacc;
    __syncthreads();

    if (threadIdx.x == 0) {
        double total = 0.0;
        #pragma unroll
        for (int w = 0; w < FIN_THREADS / 32; w++) total += dwarp[w];
        const double scale = 1.0 / (524288.0 * 8.0);  // mean(C,H,Wd), /half_win
        out[0] = (float)(total * scale);
    }
}

extern "C" void kernel_launch(void* const* d_in, const int* in_sizes, int n_in,
                              void* d_out, int out_size)
{
    const float4* out4 = (const float4*)d_in[0];
    const float4* tgt4 = (const float4*)d_in[1];
    float* o = (float*)d_out;

    cont_loss_partial_kernel<<<NBLOCKS, NTHREADS>>>(out4, tgt4);

    // Secondary with programmatic dependent launch: launch overlaps primary.
    cudaLaunchConfig_t cfg = {};
    cfg.gridDim  = dim3(1, 1, 1);
    cfg.blockDim = dim3(FIN_THREADS, 1, 1);
    cfg.dynamicSmemBytes = 0;
    cfg.stream = 0;  // same (legacy default) stream as the primary

    cudaLaunchAttribute attr[1];
    attr[0].id = cudaLaunchAttributeProgrammaticStreamSerialization;
    attr[0].val.programmaticStreamSerializationAllowed = 1;
    cfg.attrs = attr;
    cfg.numAttrs = 1;

    cudaLaunchKernelEx(&cfg, cont_loss_final_kernel, o);
}

// round 9
// speedup vs baseline: 1.0251x; 1.0251x over previous
#include <cuda_runtime.h>
#include <cuda_bf16.h>

// loss = sum_{b,c,s,h,w} (out[b,c,2s,h,w] - target[b,c,2s+1,h,w])^2 / (C*H*Wd * W/2)
// B=8, C=32, W=16 (s=0..7), H=128, Wd=128.
//
// 2048 slabs (g = flattened b,c,s). Slab g:
//   out float4 base : out4 + (g<<13)          (4096 float4 = 64 KB)
//   tgt float4 base : tgt4 + (g<<13) + 4096   (4096 float4 = 64 KB)
//
// Scale = 1/(524288*8) = 2^-22 EXACT power of two -> folded into each block
// partial with zero rounding error. Each CTA fires ONE returnless
// red.add.relaxed.gpu.f32 into d_out[0] and retires: no counter, no fence,
// no spinner, no second kernel. d_out is zeroed by a cudaMemsetAsync node at
// the head of the graph so every replay is idempotent.

#define NBLOCKS 2048
#define NTHREADS 256
#define PER_THREAD 16   // 4096 / 256

__global__ __launch_bounds__(NTHREADS) void cont_loss_kernel(
    const float4* __restrict__ out4, const float4* __restrict__ tgt4,
    float* __restrict__ result)
{
    const long long base = ((long long)blockIdx.x << 13);
    const float4* __restrict__ op = out4 + base + threadIdx.x;
    const float4* __restrict__ tp = tgt4 + base + 4096 + threadIdx.x;

    float a0 = 0.0f, a1 = 0.0f, a2 = 0.0f, a3 = 0.0f;
    #pragma unroll
    for (int k = 0; k < PER_THREAD; k++) {
        float4 o = op[k * NTHREADS];
        float4 t = tp[k * NTHREADS];
        float d0 = o.x - t.x;
        float d1 = o.y - t.y;
        float d2 = o.z - t.z;
        float d3 = o.w - t.w;
        a0 = fmaf(d0, d0, a0);
        a1 = fmaf(d1, d1, a1);
        a2 = fmaf(d2, d2, a2);
        a3 = fmaf(d3, d3, a3);
    }
    float acc = (a0 + a1) + (a2 + a3);

    // deterministic in-block reduction (same structure as the 39.6us kernel)
    __shared__ float sbuf[NTHREADS];
    sbuf[threadIdx.x] = acc;
    __syncthreads();
    #pragma unroll
    for (int ofs = NTHREADS / 2; ofs > 0; ofs >>= 1) {
        if (threadIdx.x < ofs) sbuf[threadIdx.x] += sbuf[threadIdx.x + ofs];
        __syncthreads();
    }

    if (threadIdx.x == 0) {
        // 2^-22: exact scaling (exponent shift only)
        float scaled = sbuf[0] * 2.384185791015625e-07f;
        // fire-and-forget returnless reduction into the output scalar
        asm volatile("red.add.relaxed.gpu.f32 [%0], %1;"
                     :: "l"(result), "f"(scaled) : "memory");
    }
}

extern "C" void kernel_launch(void* const* d_in, const int* in_sizes, int n_in,
                              void* d_out, int out_size)
{
    const float4* out4 = (const float4*)d_in[0];
    const float4* tgt4 = (const float4*)d_in[1];
    float* o = (float*)d_out;

    // Reset accumulator every launch (graph-captured, replay-idempotent).
    cudaMemsetAsync(o, 0, sizeof(float), 0);

    cont_loss_kernel<<<NBLOCKS, NTHREADS>>>(out4, tgt4, o);
}

// round 10
// speedup vs baseline: 1.0295x; 1.0043x over previous
#include <cuda_runtime.h>
#include <cuda_bf16.h>

// loss = sum_{b,c,s,h,w} (out[b,c,2s,h,w] - target[b,c,2s+1,h,w])^2 / (C*H*Wd * W/2)
// B=8, C=32, W=16 (s=0..7), H=128, Wd=128.
//
// 2048 slabs (g = flattened b,c,s). Slab g:
//   out float4 base : out4 + (g<<13)          (4096 float4 = 64 KB)
//   tgt float4 base : tgt4 + (g<<13) + 4096   (4096 float4 = 64 KB)
//
// SINGLE-WAVE grid: 1024 CTAs x 2 slabs (residency limit is 1184 CTAs at
// 256 thr/CTA -> all CTAs co-resident; no wave-2 transition, no drain skew).
// Scale 2^-22 is exact -> folded per-CTA; ONE returnless red.add per CTA into
// d_out[0]; head cudaMemsetAsync keeps graph replays idempotent.

#define NBLOCKS 1024
#define SLABS_PER_CTA 2
#define NTHREADS 256
#define PER_THREAD 16          // 4096 / 256
#define SLAB_STRIDE4 8192      // float4 region per slab (1<<13)

__global__ __launch_bounds__(NTHREADS) void cont_loss_kernel(
    const float4* __restrict__ out4, const float4* __restrict__ tgt4,
    float* __restrict__ result)
{
    const long long base = ((long long)blockIdx.x * SLABS_PER_CTA) << 13;
    const float4* __restrict__ op = out4 + base + threadIdx.x;
    const float4* __restrict__ tp = tgt4 + base + 4096 + threadIdx.x;

    float a0 = 0.0f, a1 = 0.0f, a2 = 0.0f, a3 = 0.0f;
    #pragma unroll
    for (int j = 0; j < SLABS_PER_CTA; j++) {
        #pragma unroll
        for (int k = 0; k < PER_THREAD; k++) {
            float4 o = op[j * SLAB_STRIDE4 + k * NTHREADS];
            float4 t = tp[j * SLAB_STRIDE4 + k * NTHREADS];
            float d0 = o.x - t.x;
            float d1 = o.y - t.y;
            float d2 = o.z - t.z;
            float d3 = o.w - t.w;
            a0 = fmaf(d0, d0, a0);
            a1 = fmaf(d1, d1, a1);
            a2 = fmaf(d2, d2, a2);
            a3 = fmaf(d3, d3, a3);
        }
    }
    float acc = (a0 + a1) + (a2 + a3);

    // deterministic in-block smem tree (matches the best-measured tail)
    __shared__ float sbuf[NTHREADS];
    sbuf[threadIdx.x] = acc;
    __syncthreads();
    #pragma unroll
    for (int ofs = NTHREADS / 2; ofs > 0; ofs >>= 1) {
        if (threadIdx.x < ofs) sbuf[threadIdx.x] += sbuf[threadIdx.x + ofs];
        __syncthreads();
    }

    if (threadIdx.x == 0) {
        // 2^-22: exact scaling (exponent shift only)
        float scaled = sbuf[0] * 2.384185791015625e-07f;
        asm volatile("red.add.relaxed.gpu.f32 [%0], %1;"
                     :: "l"(result), "f"(scaled) : "memory");
    }
}

extern "C" void kernel_launch(void* const* d_in, const int* in_sizes, int n_in,
                              void* d_out, int out_size)
{
    const float4* out4 = (const float4*)d_in[0];
    const float4* tgt4 = (const float4*)d_in[1];
    float* o = (float*)d_out;

    // Reset accumulator every launch (graph-captured, replay-idempotent).
    cudaMemsetAsync(o, 0, sizeof(float), 0);

    cont_loss_kernel<<<NBLOCKS, NTHREADS>>>(out4, tgt4, o);
}

// round 11
// speedup vs baseline: 1.0537x; 1.0235x over previous
#include <cuda_runtime.h>
#include <cuda_bf16.h>

// loss = sum_{b,c,s,h,w} (out[b,c,2s,h,w] - target[b,c,2s+1,h,w])^2 / (C*H*Wd * W/2)
// B=8, C=32, W=16 (s=0..7), H=128, Wd=128.
//
// 2048 slabs (g = flattened b,c,s). Slab g:
//   out float4 base : out4 + (g<<13)          (4096 float4 = 64 KB)
//   tgt float4 base : tgt4 + (g<<13) + 4096   (4096 float4 = 64 KB)
//
// Completion protocol: ONE red.add.relaxed.gpu.u64 per CTA into a packed word:
//   bits [0,44)  : fixed-point block sum (raw * 2^12; total ~2^38 << 2^44)
//   bits [44,..) : arrival count (each CTA adds 1<<44)
// Single address -> L2 total order -> spinner needs no acquire/release/fence
// (release semantics measured as the bandwidth poison in R2/R4/R6).
// Integer accumulation is deterministic; quantization rel_err ~4e-9.
// Spinner writes d_out and re-arms the word -> no memset node, replay-safe.

#define NBLOCKS 2048
#define NTHREADS 256
#define PER_THREAD 16   // 4096 / 256

#define COUNT_SHIFT 44
#define SUM_MASK ((1ULL << COUNT_SHIFT) - 1ULL)
#define FIX_SCALE 4096.0   // 2^12

__device__ unsigned long long g_packed = 0ULL;  // re-armed by spinner each launch

__global__ __launch_bounds__(NTHREADS) void cont_loss_kernel(
    const float4* __restrict__ out4, const float4* __restrict__ tgt4,
    float* __restrict__ result)
{
    const long long base = ((long long)blockIdx.x << 13);
    const float4* __restrict__ op = out4 + base + threadIdx.x;
    const float4* __restrict__ tp = tgt4 + base + 4096 + threadIdx.x;

    float a0 = 0.0f, a1 = 0.0f, a2 = 0.0f, a3 = 0.0f;
    #pragma unroll
    for (int k = 0; k < PER_THREAD; k++) {
        float4 o = op[k * NTHREADS];
        float4 t = tp[k * NTHREADS];
        float d0 = o.x - t.x;
        float d1 = o.y - t.y;
        float d2 = o.z - t.z;
        float d3 = o.w - t.w;
        a0 = fmaf(d0, d0, a0);
        a1 = fmaf(d1, d1, a1);
        a2 = fmaf(d2, d2, a2);
        a3 = fmaf(d3, d3, a3);
    }
    float acc = (a0 + a1) + (a2 + a3);

    // deterministic in-block smem tree
    __shared__ float sbuf[NTHREADS];
    sbuf[threadIdx.x] = acc;
    __syncthreads();
    #pragma unroll
    for (int ofs = NTHREADS / 2; ofs > 0; ofs >>= 1) {
        if (threadIdx.x < ofs) sbuf[threadIdx.x] += sbuf[threadIdx.x + ofs];
        __syncthreads();
    }

    if (threadIdx.x == 0) {
        // fixed-point encode (exact integer accumulation across CTAs)
        unsigned long long fixed =
            (unsigned long long)__double2ll_rn((double)sbuf[0] * FIX_SCALE);
        unsigned long long pkt = fixed + (1ULL << COUNT_SHIFT);
        asm volatile("red.add.relaxed.gpu.u64 [%0], %1;"
                     :: "l"(&g_packed), "l"(pkt) : "memory");

        // Spinner: same-address polling (L2 total order => no fences needed).
        if (blockIdx.x == NBLOCKS - 1) {
            unsigned long long v;
            do {
                __nanosleep(100);
                asm volatile("ld.relaxed.gpu.u64 %0, [%1];"
                             : "=l"(v) : "l"(&g_packed));
            } while ((v >> COUNT_SHIFT) < (unsigned long long)NBLOCKS);

            double total = (double)(long long)(v & SUM_MASK) / FIX_SCALE;
            const double scale = 1.0 / (524288.0 * 8.0);  // 2^-22, exact
            result[0] = (float)(total * scale);

            // re-arm for next graph replay (all CTAs already counted)
            asm volatile("st.relaxed.gpu.u64 [%0], %1;"
                         :: "l"(&g_packed), "l"(0ULL) : "memory");
        }
    }
}

extern "C" void kernel_launch(void* const* d_in, const int* in_sizes, int n_in,
                              void* d_out, int out_size)
{
    const float4* out4 = (const float4*)d_in[0];
    const float4* tgt4 = (const float4*)d_in[1];
    float* o = (float*)d_out;

    cont_loss_kernel<<<NBLOCKS, NTHREADS>>>(out4, tgt4, o);
}